// round 10
// baseline (speedup 1.0000x reference)
#include <cuda_runtime.h>
#include <cuda_fp16.h>
#include <cstdint>

#define N 8192
#define D 128
#define NBLK 64               // 64 tiles of 128 rows/cols
#define TILEB 32768           // one 128x128 fp16 tile, bytes
#define NCTA 2080             // upper-triangle tile pairs (64*65/2)
#define NCTAS 152             // persistent CTAs, occ 1
#define EPS2 0.25f
#define LOG2E 1.4426950408889634f
#define TENLOG2E 14.426950408889634f

// ---------------- device scratch ----------------
__device__ uint4  g_hf[NBLK * 2048];   // fp16 tiles, ldmatrix-swizzled
__device__ float4 g_pos4[N];           // (x,y,z,|p|^2)
__device__ float  g_dse[NCTA * 128], g_dsp[NCTA * 128], g_dct[NCTA * 128];  // row (block I) partials
__device__ float  g_tse[NCTA * 128], g_tsp[NCTA * 128], g_tct[NCTA * 128];  // col (block J) partials
__device__ float  g_partL[64], g_partV[64];

// ---------------- portable PTX helpers ----------------
#define CP16(dst, src) \
    asm volatile("cp.async.cg.shared.global [%0], [%1], 16;\n" :: "r"(dst), "l"(src) : "memory")
#define CP_COMMIT() asm volatile("cp.async.commit_group;\n" ::: "memory")
#define CP_WAIT0()  asm volatile("cp.async.wait_group 0;\n" ::: "memory")

#define LDSM4(r0, r1, r2, r3, addr) \
    asm volatile("ldmatrix.sync.aligned.m8n8.x4.shared.b16 {%0,%1,%2,%3}, [%4];" \
                 : "=r"(r0), "=r"(r1), "=r"(r2), "=r"(r3) : "r"(addr))

#define MMA16816(d, a, b0, b1) \
    asm volatile("mma.sync.aligned.m16n8k16.row.col.f32.f16.f16.f32 " \
                 "{%0,%1,%2,%3}, {%4,%5,%6,%7}, {%8,%9}, {%0,%1,%2,%3};" \
                 : "+f"((d)[0]), "+f"((d)[1]), "+f"((d)[2]), "+f"((d)[3]) \
                 : "r"((a)[0]), "r"((a)[1]), "r"((a)[2]), "r"((a)[3]), "r"(b0), "r"(b1))

__device__ __host__ __forceinline__ uint32_t swz(uint32_t x, uint32_t c16) {
    return (c16 & 8u) | ((c16 & 7u) ^ x);
}

// ---------------- prep: normalize + fp16 convert + swizzled tile store ----------------
__global__ void prep_kernel(const float* __restrict__ h) {
    int row  = blockIdx.x * 8 + (threadIdx.x >> 5);
    int lane = threadIdx.x & 31;
    float4 v = ((const float4*)h)[row * 32 + lane];
    float ss = v.x * v.x + v.y * v.y + v.z * v.z + v.w * v.w;
    #pragma unroll
    for (int o = 16; o; o >>= 1) ss += __shfl_xor_sync(0xffffffffu, ss, o);
    float inv = 1.0f / fmaxf(sqrtf(ss), 1e-12f);
    float x[4] = {v.x * inv, v.y * inv, v.z * inv, v.w * inv};
    unsigned short hb[4];
    #pragma unroll
    for (int j = 0; j < 4; j++) hb[j] = __half_as_ushort(__float2half_rn(x[j]));
    uint2 hu = make_uint2((uint32_t)hb[0] | ((uint32_t)hb[1] << 16),
                          (uint32_t)hb[2] | ((uint32_t)hb[3] << 16));
    int blk = row >> 7, r = row & 127;
    uint32_t c16 = (uint32_t)(lane >> 1);
    uint32_t soff = (uint32_t)r * 256u + swz((uint32_t)(r & 7), c16) * 16u
                    + (uint32_t)(lane & 1) * 8u;
    *(uint2*)((char*)g_hf + (size_t)blk * TILEB + soff) = hu;
}

__global__ void pos_kernel(const float* __restrict__ pos) {
    int i = blockIdx.x * blockDim.x + threadIdx.x;
    if (i < N) {
        float x = pos[3 * i], y = pos[3 * i + 1], z = pos[3 * i + 2];
        g_pos4[i] = make_float4(x, y, z, x * x + y * y + z * z);
    }
}

// ---------------- main kernel: persistent, intra-warp pipelined halves ----------------
// smem: A 0..32K | B buf0 32K..64K | B buf1 64K..96K | red @96K (9216 B)
#define ASM 0
#define BBUF(b) (32768 + (b) * 32768)
#define RED 98304
#define SMEM_REQ (RED + 9216)   // 107520

__device__ __forceinline__ void load_tile16(uint32_t dst, int blk, int tid) {
    const char* gh = (const char*)g_hf + (size_t)blk * TILEB;
    #pragma unroll
    for (int i = 0; i < 8; i++) {
        uint32_t o = (uint32_t)(tid * 128 + i * 16);
        CP16(dst + o, gh + o);
    }
}

__global__ void __launch_bounds__(256, 1) main_kernel() {
    extern __shared__ __align__(128) char smem[];
    const uint32_t sbase = (uint32_t)__cvta_generic_to_shared(smem);
    float* rbuf_se = (float*)(smem + RED);
    float* rbuf_sp = rbuf_se + 512;
    float* rbuf_ct = rbuf_sp + 512;
    float* cbuf_se = rbuf_ct + 512;
    float* cbuf_sp = cbuf_se + 256;
    float* cbuf_ct = cbuf_sp + 256;

    const int tid = threadIdx.x, wid = tid >> 5, lane = tid & 31;
    const int warpRow = wid >> 2, warpCol = wid & 3;

    const int p0 = (int)((long long)blockIdx.x * NCTA / NCTAS);
    const int p1 = (int)((long long)(blockIdx.x + 1) * NCTA / NCTAS);
    if (p0 >= p1) return;

    // decode p0 -> (I, J)
    int I = 0, t = p0;
    while (t >= NBLK - I) { t -= NBLK - I; I++; }
    int J = I + t;

    // ---- fragment address constants ----
    uint32_t aAddr[4], axr[4];
    #pragma unroll
    for (int mt = 0; mt < 4; mt++) {
        uint32_t r = (uint32_t)(warpRow * 64 + mt * 16 + (lane & 15));
        aAddr[mt] = sbase + ASM + r * 256u;
        axr[mt]   = r & 7u;
    }
    const uint32_t aSel = (uint32_t)((lane >> 4) & 1);
    uint32_t bOff[2], bxr[2];
    #pragma unroll
    for (int ntp = 0; ntp < 2; ntp++) {
        uint32_t n = (uint32_t)(warpCol * 32 + ntp * 16 + ((lane >> 4) & 1) * 8 + (lane & 7));
        bOff[ntp] = n * 256u;
        bxr[ntp]  = n & 7u;
    }
    const uint32_t bSel = (uint32_t)((lane >> 3) & 1);

    // ---- MMA burst for one column half h (16 cols/warp) into ac ----
    auto mma_half = [&](float (&ac)[4][2][4], const int h, uint32_t baseB) {
        #pragma unroll
        for (int mt = 0; mt < 4; mt++)
            #pragma unroll
            for (int ntl = 0; ntl < 2; ntl++)
                #pragma unroll
                for (int c = 0; c < 4; c++) ac[mt][ntl][c] = 0.f;
        #pragma unroll 2
        for (int step = 0; step < 8; step++) {
            const uint32_t c16a = (uint32_t)(2 * step) + aSel;
            const uint32_t c16b = (uint32_t)(2 * step) + bSel;
            uint32_t bh[4], af[4][4];
            LDSM4(bh[0], bh[1], bh[2], bh[3], baseB + bOff[h] + (swz(bxr[h], c16b) << 4));
            #pragma unroll
            for (int mt = 0; mt < 4; mt++)
                LDSM4(af[mt][0], af[mt][1], af[mt][2], af[mt][3],
                      aAddr[mt] + (swz(axr[mt], c16a) << 4));
            #pragma unroll
            for (int mt = 0; mt < 4; mt++)
                #pragma unroll
                for (int ntl = 0; ntl < 2; ntl++)
                    MMA16816(ac[mt][ntl], af[mt], bh[ntl * 2], bh[ntl * 2 + 1]);
        }
    };

    // persistent row accumulators (Σexp, Σsim_pos, count) across the two halves
    float rse[8], rsp[8], rct[8];
    #pragma unroll
    for (int i = 0; i < 8; i++) { rse[i] = 0.f; rsp[i] = 0.f; rct[i] = 0.f; }

    // ---- epilogue of one half: fold 32 sims/lane into row + col accumulators ----
    auto epi_half = [&](float (&ac)[4][2][4], const int h, int ti, int tj) {
        const int rowBase = ti * 128, colBase = tj * 128;
        float cse[4], csp[4], cct[4];
        #pragma unroll
        for (int i = 0; i < 4; i++) { cse[i] = 0.f; csp[i] = 0.f; cct[i] = 0.f; }
        float4 pb[4];
        #pragma unroll
        for (int ntl = 0; ntl < 2; ntl++)
            #pragma unroll
            for (int ce = 0; ce < 2; ce++)
                pb[ntl * 2 + ce] = __ldg(&g_pos4[colBase + warpCol * 32 + h * 16
                                                + ntl * 8 + (lane & 3) * 2 + ce]);
        #pragma unroll
        for (int mt = 0; mt < 4; mt++) {
            #pragma unroll
            for (int rs = 0; rs < 2; rs++) {
                const int idx = mt * 2 + rs;
                const int gi = rowBase + warpRow * 64 + mt * 16 + (lane >> 2) + rs * 8;
                const float4 A = __ldg(&g_pos4[gi]);
                #pragma unroll
                for (int ntl = 0; ntl < 2; ntl++) {
                    #pragma unroll
                    for (int ce = 0; ce < 2; ce++) {
                        float sim = ac[mt][ntl][rs * 2 + ce];
                        int j = colBase + warpCol * 32 + h * 16 + ntl * 8 + (lane & 3) * 2 + ce;
                        float e, arg = fmaf(sim, TENLOG2E, -TENLOG2E);
                        asm("ex2.approx.ftz.f32 %0, %1;" : "=f"(e) : "f"(arg));
                        float4 B = pb[ntl * 2 + ce];
                        bool self = (gi == j);
                        float dot = A.x * B.x + A.y * B.y + A.z * B.z;
                        float d2  = A.w + B.w - 2.0f * dot;
                        bool ispos = (d2 < EPS2) && !self;
                        float ev = self ? 0.0f : e;
                        float pv = ispos ? sim : 0.0f;
                        float cv = ispos ? 1.0f : 0.0f;
                        rse[idx] += ev; rsp[idx] += pv; rct[idx] += cv;
                        int ci = ntl * 2 + ce;
                        cse[ci] += ev; csp[ci] += pv; cct[ci] += cv;
                    }
                }
            }
        }
        // col reduce: 8 lanes (lane>>2) share each column; write this half's cbuf section
        #pragma unroll
        for (int ci = 0; ci < 4; ci++) {
            float a = cse[ci], b = csp[ci], c = cct[ci];
            #pragma unroll
            for (int o = 16; o >= 4; o >>= 1) {
                a += __shfl_down_sync(0xffffffffu, a, o);
                b += __shfl_down_sync(0xffffffffu, b, o);
                c += __shfl_down_sync(0xffffffffu, c, o);
            }
            if (lane < 4) {
                int cl = h * 16 + (ci >> 1) * 8 + lane * 2 + (ci & 1);
                cbuf_se[wid * 32 + cl] = a;
                cbuf_sp[wid * 32 + cl] = b;
                cbuf_ct[wid * 32 + cl] = c;
            }
        }
        if (h == 1) {   // rows complete: reduce over 4 lanes, stash, reset
            #pragma unroll
            for (int idx = 0; idx < 8; idx++) {
                float a = rse[idx], b = rsp[idx], c = rct[idx];
                a += __shfl_down_sync(0xffffffffu, a, 2, 4);
                b += __shfl_down_sync(0xffffffffu, b, 2, 4);
                c += __shfl_down_sync(0xffffffffu, c, 2, 4);
                a += __shfl_down_sync(0xffffffffu, a, 1, 4);
                b += __shfl_down_sync(0xffffffffu, b, 1, 4);
                c += __shfl_down_sync(0xffffffffu, c, 1, 4);
                if ((lane & 3) == 0) {
                    int rl = (idx >> 1) * 16 + (idx & 1) * 8 + (lane >> 2);
                    rbuf_se[wid * 64 + rl] = a;
                    rbuf_sp[wid * 64 + rl] = b;
                    rbuf_ct[wid * 64 + rl] = c;
                }
                rse[idx] = 0.f; rsp[idx] = 0.f; rct[idx] = 0.f;
            }
        }
    };

    auto combine_write = [&](int pp, bool dg) {
        const int slot = pp * 128;
        if (tid < 128) {
            int half = tid >> 6, loc = tid & 63;
            float a = 0.f, b = 0.f, c = 0.f;
            #pragma unroll
            for (int wc = 0; wc < 4; wc++) {
                int w = half * 4 + wc;
                a += rbuf_se[w * 64 + loc];
                b += rbuf_sp[w * 64 + loc];
                c += rbuf_ct[w * 64 + loc];
            }
            g_dse[slot + tid] = a; g_dsp[slot + tid] = b; g_dct[slot + tid] = c;
        } else if (!dg) {
            int tcl = tid - 128, wc = tcl >> 5, c5 = tcl & 31;
            float a = cbuf_se[wc * 32 + c5] + cbuf_se[(4 + wc) * 32 + c5];
            float b = cbuf_sp[wc * 32 + c5] + cbuf_sp[(4 + wc) * 32 + c5];
            float c = cbuf_ct[wc * 32 + c5] + cbuf_ct[(4 + wc) * 32 + c5];
            g_tse[slot + tcl] = a; g_tsp[slot + tcl] = b; g_tct[slot + tcl] = c;
        }
    };

    // ---- prologue: A(p0) + B(p0) into buf 0 ----
    load_tile16(sbase + ASM, I, tid);
    load_tile16(sbase + BBUF(0), J, tid);
    CP_COMMIT();

    float acc0[4][2][4], acc1[4][2][4];
    int buf = 0, lI = I, lJ = J;

    for (int p = p0; p < p1; p++) {
        int nI = I, nJ = J + 1;
        if (nJ == NBLK) { nI = I + 1; nJ = nI; }
        const bool havenext = (p + 1 < p1);
        const bool nextSame = havenext && (nI == I);

        CP_WAIT0();
        __syncthreads();                       // S1: B(p)/A ready; prior combine done
        const uint32_t baseB = sbase + BBUF(buf);

        mma_half(acc0, 0, baseB);              // MMA h0 (tensor pipe fills)

        if (p > p0) {                          // hide under MMA h0 drain
            epi_half(acc1, 1, lI, lJ);
            __syncthreads();                   // S2: rbuf/cbuf complete
            combine_write(p - 1, lI == lJ);
        }

        mma_half(acc1, 1, baseB);              // MMA h1
        __syncthreads();                       // S3: all LDSMs of this pair done

        if (havenext) {                        // safe to overwrite smem now
            if (!nextSame) load_tile16(sbase + ASM, nI, tid);
            load_tile16(sbase + BBUF(buf ^ 1), nJ, tid);
            CP_COMMIT();
        }

        epi_half(acc0, 0, I, J);               // hide under MMA h1 drain + loads

        lI = I; lJ = J; I = nI; J = nJ; buf ^= 1;
    }

    // drain: epilogue h1 + combine of the last pair
    epi_half(acc1, 1, lI, lJ);
    __syncthreads();
    combine_write(p1 - 1, lI == lJ);
}

// ---------------- final reduction over triangle slots ----------------
__device__ __forceinline__ int tri_base(int I) { return I * NBLK - (I * (I - 1)) / 2; }

// grid 64 (one per anchor tile-row R), block 1024: tid = (slotGroup<<7) | anchorLocal
__global__ void final_partial_kernel() {
    __shared__ float s_se[8][128], s_sp[8][128], s_ct[8][128];
    __shared__ float sL[4], sV[4];
    const int tid = threadIdx.x;
    const int rr = tid & 127, sg = tid >> 7;
    const int R = blockIdx.x;
    const int nd = NBLK - R;
    float se = 0.f, sp = 0.f, c = 0.f;
    #pragma unroll
    for (int k = 0; k < 8; k++) {
        int s = sg * 8 + k;
        int id; const float *pse, *psp, *pct;
        if (s < nd) { id = tri_base(R) + s;            pse = g_dse; psp = g_dsp; pct = g_dct; }
        else        { int I = s - nd;
                      id = tri_base(I) + (R - I);      pse = g_tse; psp = g_tsp; pct = g_tct; }
        se += pse[id * 128 + rr]; sp += psp[id * 128 + rr]; c += pct[id * 128 + rr];
    }
    s_se[sg][rr] = se; s_sp[sg][rr] = sp; s_ct[sg][rr] = c;
    __syncthreads();
    if (tid < 128) {
        float a = 0.f, b = 0.f, cc = 0.f;
        #pragma unroll
        for (int g = 0; g < 8; g++) { a += s_se[g][tid]; b += s_sp[g][tid]; cc += s_ct[g][tid]; }
        float lse = logf(a) + 10.0f;
        float L = 0.f, V = 0.f;
        if (cc > 0.0f) { L = -(10.0f * b - cc * lse) / cc; V = 1.0f; }  // sp stored as Σsim
        #pragma unroll
        for (int o = 16; o; o >>= 1) {
            L += __shfl_down_sync(0xffffffffu, L, o);
            V += __shfl_down_sync(0xffffffffu, V, o);
        }
        if ((tid & 31) == 0) { sL[tid >> 5] = L; sV[tid >> 5] = V; }
    }
    __syncthreads();
    if (tid == 0) {
        g_partL[blockIdx.x] = sL[0] + sL[1] + sL[2] + sL[3];
        g_partV[blockIdx.x] = sV[0] + sV[1] + sV[2] + sV[3];
    }
}

__global__ void final_combine_kernel(float* __restrict__ out) {
    int tid = threadIdx.x;   // 32 threads
    float a = g_partL[tid] + g_partL[tid + 32];
    float b = g_partV[tid] + g_partV[tid + 32];
    #pragma unroll
    for (int o = 16; o; o >>= 1) {
        a += __shfl_down_sync(0xffffffffu, a, o);
        b += __shfl_down_sync(0xffffffffu, b, o);
    }
    if (tid == 0) out[0] = a / fmaxf(b, 1.0f);
}

// ---------------- launch ----------------
extern "C" void kernel_launch(void* const* d_in, const int* in_sizes, int n_in,
                              void* d_out, int out_size) {
    const float* h   = (const float*)d_in[0];
    const float* pos = (const float*)d_in[1];
    if (n_in >= 2 && in_sizes[0] < in_sizes[1]) {
        const float* t = h; h = pos; pos = t;
    }
    float* out = (float*)d_out;

    prep_kernel<<<N / 8, 256>>>(h);
    pos_kernel<<<N / 256, 256>>>(pos);

    cudaFuncSetAttribute(main_kernel, cudaFuncAttributeMaxDynamicSharedMemorySize, SMEM_REQ);
    main_kernel<<<NCTAS, 256, SMEM_REQ>>>();

    final_partial_kernel<<<64, 1024>>>();
    final_combine_kernel<<<1, 32>>>(out);
}

// round 11
// speedup vs baseline: 1.2184x; 1.2184x over previous
#include <cuda_runtime.h>
#include <cuda_fp16.h>
#include <cstdint>

#define N 8192
#define D 128
#define NBLK 64               // 64 tiles of 128 rows/cols
#define TILEB 32768           // one 128x128 fp16 tile, bytes
#define NCTA 2080             // upper-triangle tile pairs (64*65/2)
#define NCTAS 304             // persistent CTAs: 2 per SM on 152 SMs
#define EPS2 0.25f
#define LOG2E 1.4426950408889634f
#define TENLOG2E 14.426950408889634f

// ---------------- device scratch ----------------
__device__ uint4  g_hf[NBLK * 2048];   // fp16 tiles, ldmatrix-swizzled
__device__ float4 g_pos4[N];           // (x,y,z,|p|^2)
__device__ float  g_dse[NCTA * 128], g_dsp[NCTA * 128], g_dct[NCTA * 128];  // row (block I) partials
__device__ float  g_tse[NCTA * 128], g_tsp[NCTA * 128], g_tct[NCTA * 128];  // col (block J) partials
__device__ float  g_partL[256], g_partV[256];

// ---------------- portable PTX helpers ----------------
#define CP16(dst, src) \
    asm volatile("cp.async.cg.shared.global [%0], [%1], 16;\n" :: "r"(dst), "l"(src) : "memory")
#define CP_COMMIT() asm volatile("cp.async.commit_group;\n" ::: "memory")
#define CP_WAIT0()  asm volatile("cp.async.wait_group 0;\n" ::: "memory")

#define LDSM4(r0, r1, r2, r3, addr) \
    asm volatile("ldmatrix.sync.aligned.m8n8.x4.shared.b16 {%0,%1,%2,%3}, [%4];" \
                 : "=r"(r0), "=r"(r1), "=r"(r2), "=r"(r3) : "r"(addr))

#define MMA16816(d, a, b0, b1) \
    asm volatile("mma.sync.aligned.m16n8k16.row.col.f32.f16.f16.f32 " \
                 "{%0,%1,%2,%3}, {%4,%5,%6,%7}, {%8,%9}, {%0,%1,%2,%3};" \
                 : "+f"((d)[0]), "+f"((d)[1]), "+f"((d)[2]), "+f"((d)[3]) \
                 : "r"((a)[0]), "r"((a)[1]), "r"((a)[2]), "r"((a)[3]), "r"(b0), "r"(b1))

__device__ __host__ __forceinline__ uint32_t swz(uint32_t x, uint32_t c16) {
    return (c16 & 8u) | ((c16 & 7u) ^ x);
}

// ---------------- prep: normalize + fp16 convert + swizzled store + pos pack ----------------
__global__ void prep_kernel(const float* __restrict__ h, const float* __restrict__ pos) {
    int row  = blockIdx.x * 8 + (threadIdx.x >> 5);
    int lane = threadIdx.x & 31;
    float4 v = ((const float4*)h)[row * 32 + lane];
    float ss = v.x * v.x + v.y * v.y + v.z * v.z + v.w * v.w;
    #pragma unroll
    for (int o = 16; o; o >>= 1) ss += __shfl_xor_sync(0xffffffffu, ss, o);
    float inv = 1.0f / fmaxf(sqrtf(ss), 1e-12f);
    float x[4] = {v.x * inv, v.y * inv, v.z * inv, v.w * inv};
    unsigned short hb[4];
    #pragma unroll
    for (int j = 0; j < 4; j++) hb[j] = __half_as_ushort(__float2half_rn(x[j]));
    uint2 hu = make_uint2((uint32_t)hb[0] | ((uint32_t)hb[1] << 16),
                          (uint32_t)hb[2] | ((uint32_t)hb[3] << 16));
    int blk = row >> 7, r = row & 127;
    uint32_t c16 = (uint32_t)(lane >> 1);
    uint32_t soff = (uint32_t)r * 256u + swz((uint32_t)(r & 7), c16) * 16u
                    + (uint32_t)(lane & 1) * 8u;
    *(uint2*)((char*)g_hf + (size_t)blk * TILEB + soff) = hu;
    if (lane == 0) {
        float px = pos[3 * row], py = pos[3 * row + 1], pz = pos[3 * row + 2];
        g_pos4[row] = make_float4(px, py, pz, px * px + py * py + pz * pz);
    }
}

// ---------------- main kernel: persistent, pipelined tile pairs, occ 2 ----------------
// smem: A 0..32K | B buf0 32K..64K | B buf1 64K..96K | red @96K (9216 B)
#define ASM 0
#define BBUF(b) (32768 + (b) * 32768)
#define RED 98304
#define SMEM_REQ (RED + 9216)   // 107520

__device__ __forceinline__ void load_tile16(uint32_t dst, int blk, int tid) {
    const char* gh = (const char*)g_hf + (size_t)blk * TILEB;
    #pragma unroll
    for (int i = 0; i < 8; i++) {
        uint32_t o = (uint32_t)(tid * 128 + i * 16);
        CP16(dst + o, gh + o);
    }
}

__global__ void __launch_bounds__(256, 2) main_kernel() {
    extern __shared__ __align__(128) char smem[];
    const uint32_t sbase = (uint32_t)__cvta_generic_to_shared(smem);
    float* rbuf_se = (float*)(smem + RED);
    float* rbuf_sp = rbuf_se + 512;
    float* rbuf_ct = rbuf_sp + 512;
    float* cbuf_se = rbuf_ct + 512;
    float* cbuf_sp = cbuf_se + 256;
    float* cbuf_ct = cbuf_sp + 256;

    const int tid = threadIdx.x, wid = tid >> 5, lane = tid & 31;
    const int warpRow = wid >> 2, warpCol = wid & 3;

    // pair range for this persistent CTA
    const int p0 = (int)((long long)blockIdx.x * NCTA / NCTAS);
    const int p1 = (int)((long long)(blockIdx.x + 1) * NCTA / NCTAS);
    if (p0 >= p1) return;

    // decode p0 -> (I, J)
    int I = 0, t = p0;
    while (t >= NBLK - I) { t -= NBLK - I; I++; }
    int J = I + t;

    // ---- fragment address constants ----
    uint32_t aAddr[4], axr[4];
    #pragma unroll
    for (int mt = 0; mt < 4; mt++) {
        uint32_t r = (uint32_t)(warpRow * 64 + mt * 16 + (lane & 15));
        aAddr[mt] = sbase + ASM + r * 256u;
        axr[mt]   = r & 7u;
    }
    const uint32_t aSel = (uint32_t)((lane >> 4) & 1);
    uint32_t bOff[2], bxr[2];
    #pragma unroll
    for (int ntp = 0; ntp < 2; ntp++) {
        uint32_t n = (uint32_t)(warpCol * 32 + ntp * 16 + ((lane >> 4) & 1) * 8 + (lane & 7));
        bOff[ntp] = n * 256u;
        bxr[ntp]  = n & 7u;
    }
    const uint32_t bSel = (uint32_t)((lane >> 3) & 1);

    // ---- prologue: A(I) + B(J) into buf 0 ----
    load_tile16(sbase + ASM, I, tid);
    load_tile16(sbase + BBUF(0), J, tid);
    CP_COMMIT();

    int buf = 0;
    for (int p = p0; p < p1; p++) {
        int nI = I, nJ = J + 1;
        if (nJ == NBLK) { nI = I + 1; nJ = nI; }
        const bool havenext = (p + 1 < p1);
        const bool nextSame = havenext && (nI == I);

        CP_WAIT0();
        __syncthreads();

        // prefetch next B now if A stays resident (overlaps the GEMM)
        if (nextSame) {
            load_tile16(sbase + BBUF(buf ^ 1), nJ, tid);
            CP_COMMIT();
        }

        const uint32_t baseB = sbase + BBUF(buf);

        float acc[4][4][4];
        #pragma unroll
        for (int mt = 0; mt < 4; mt++)
            #pragma unroll
            for (int nt = 0; nt < 4; nt++)
                #pragma unroll
                for (int c = 0; c < 4; c++) acc[mt][nt][c] = 0.f;

        // ---- single-pass fp16 GEMM ----
        #pragma unroll 2
        for (int step = 0; step < 8; step++) {
            const uint32_t c16a = (uint32_t)(2 * step) + aSel;
            const uint32_t c16b = (uint32_t)(2 * step) + bSel;
            uint32_t bh[2][4], af[4][4];
            #pragma unroll
            for (int ntp = 0; ntp < 2; ntp++) {
                uint32_t sw = swz(bxr[ntp], c16b) << 4;
                LDSM4(bh[ntp][0], bh[ntp][1], bh[ntp][2], bh[ntp][3], baseB + bOff[ntp] + sw);
            }
            #pragma unroll
            for (int mt = 0; mt < 4; mt++) {
                uint32_t sw = swz(axr[mt], c16a) << 4;
                LDSM4(af[mt][0], af[mt][1], af[mt][2], af[mt][3], aAddr[mt] + sw);
            }
            #pragma unroll
            for (int mt = 0; mt < 4; mt++)
                #pragma unroll
                for (int nt = 0; nt < 4; nt++)
                    MMA16816(acc[mt][nt], af[mt], bh[nt >> 1][(nt & 1) * 2], bh[nt >> 1][(nt & 1) * 2 + 1]);
        }

        __syncthreads();   // all warps done reading A and B[buf]

        // A-transition: load new A (+ next B), overlapping the epilogue
        if (havenext && !nextSame) {
            load_tile16(sbase + ASM, nI, tid);
            load_tile16(sbase + BBUF(buf ^ 1), nJ, tid);
            CP_COMMIT();
        }

        // ---- epilogue: fold into row (block I) AND column (block J) accumulators ----
        const int rowBase = I * 128, colBase0 = J * 128;
        const bool diag = (I == J);
        float cse[8], csp[8], cct[8];
        #pragma unroll
        for (int i = 0; i < 8; i++) { cse[i] = 0.f; csp[i] = 0.f; cct[i] = 0.f; }
        float4 pb[8];
        #pragma unroll
        for (int nt = 0; nt < 4; nt++)
            #pragma unroll
            for (int ce = 0; ce < 2; ce++)
                pb[nt * 2 + ce] = __ldg(&g_pos4[colBase0 + warpCol * 32 + nt * 8 + (lane & 3) * 2 + ce]);

        #pragma unroll
        for (int mt = 0; mt < 4; mt++) {
            #pragma unroll
            for (int rs = 0; rs < 2; rs++) {
                const int gi = rowBase + warpRow * 64 + mt * 16 + (lane >> 2) + rs * 8;
                const float4 A = __ldg(&g_pos4[gi]);
                float a_se = 0.f, a_sp = 0.f, a_ct = 0.f;     // transient row sums
                #pragma unroll
                for (int nt = 0; nt < 4; nt++) {
                    #pragma unroll
                    for (int ce = 0; ce < 2; ce++) {
                        float sim   = acc[mt][nt][rs * 2 + ce];
                        int j = colBase0 + warpCol * 32 + nt * 8 + (lane & 3) * 2 + ce;
                        float e, arg = fmaf(sim, TENLOG2E, -TENLOG2E);
                        asm("ex2.approx.ftz.f32 %0, %1;" : "=f"(e) : "f"(arg));
                        float4 B = pb[nt * 2 + ce];
                        bool self = (gi == j);
                        float dot = A.x * B.x + A.y * B.y + A.z * B.z;
                        float d2  = A.w + B.w - 2.0f * dot;
                        bool ispos = (d2 < EPS2) && !self;
                        float ev = self ? 0.0f : e;
                        float pv = ispos ? sim : 0.0f;        // store Σsim; x10 in final
                        float cv = ispos ? 1.0f : 0.0f;
                        a_se += ev; a_sp += pv; a_ct += cv;
                        int cidx = nt * 2 + ce;
                        cse[cidx] += ev; csp[cidx] += pv; cct[cidx] += cv;
                    }
                }
                // immediate row reduce over the 4 lanes (lane&3) sharing this row
                a_se += __shfl_down_sync(0xffffffffu, a_se, 2, 4);
                a_sp += __shfl_down_sync(0xffffffffu, a_sp, 2, 4);
                a_ct += __shfl_down_sync(0xffffffffu, a_ct, 2, 4);
                a_se += __shfl_down_sync(0xffffffffu, a_se, 1, 4);
                a_sp += __shfl_down_sync(0xffffffffu, a_sp, 1, 4);
                a_ct += __shfl_down_sync(0xffffffffu, a_ct, 1, 4);
                if ((lane & 3) == 0) {
                    int rl = mt * 16 + rs * 8 + (lane >> 2);
                    rbuf_se[wid * 64 + rl] = a_se;
                    rbuf_sp[wid * 64 + rl] = a_sp;
                    rbuf_ct[wid * 64 + rl] = a_ct;
                }
            }
        }

        // col reduce: 8 lanes (lane>>2) share each column
        #pragma unroll
        for (int cidx = 0; cidx < 8; cidx++) {
            float a = cse[cidx], b = csp[cidx], c = cct[cidx];
            #pragma unroll
            for (int o = 16; o >= 4; o >>= 1) {
                a += __shfl_down_sync(0xffffffffu, a, o);
                b += __shfl_down_sync(0xffffffffu, b, o);
                c += __shfl_down_sync(0xffffffffu, c, o);
            }
            if (lane < 4) {
                int cl = (cidx >> 1) * 8 + lane * 2 + (cidx & 1);
                cbuf_se[wid * 32 + cl] = a;
                cbuf_sp[wid * 32 + cl] = b;
                cbuf_ct[wid * 32 + cl] = c;
            }
        }
        __syncthreads();

        // combine across warps, write deterministic per-pair slots
        const int slot = p * 128;
        if (tid < 128) {
            int half = tid >> 6, loc = tid & 63;
            float a = 0.f, b = 0.f, c = 0.f;
            #pragma unroll
            for (int wc = 0; wc < 4; wc++) {
                int w = half * 4 + wc;
                a += rbuf_se[w * 64 + loc];
                b += rbuf_sp[w * 64 + loc];
                c += rbuf_ct[w * 64 + loc];
            }
            g_dse[slot + tid] = a; g_dsp[slot + tid] = b; g_dct[slot + tid] = c;
        } else if (!diag) {
            int tcl = tid - 128, wc = tcl >> 5, c5 = tcl & 31;
            float a = cbuf_se[wc * 32 + c5] + cbuf_se[(4 + wc) * 32 + c5];
            float b = cbuf_sp[wc * 32 + c5] + cbuf_sp[(4 + wc) * 32 + c5];
            float c = cbuf_ct[wc * 32 + c5] + cbuf_ct[(4 + wc) * 32 + c5];
            g_tse[slot + tcl] = a; g_tsp[slot + tcl] = b; g_tct[slot + tcl] = c;
        }

        I = nI; J = nJ; buf ^= 1;
    }
}

// ---------------- final reduction over triangle slots ----------------
__device__ __forceinline__ int tri_base(int I) { return I * NBLK - (I * (I - 1)) / 2; }

// grid 256 (32 anchors each; R = blockIdx>>2 constant per block), block 256:
// tid = (slotGroup<<5) | anchorLocal; each thread sums 8 of the 64 slots.
__global__ void final_partial_kernel() {
    __shared__ float s_se[8][32], s_sp[8][32], s_ct[8][32];
    const int tid = threadIdx.x;
    const int al = tid & 31, sg = tid >> 5;
    const int R = blockIdx.x >> 2;
    const int rr = (blockIdx.x & 3) * 32 + al;      // anchor-local within tile row R
    const int nd = NBLK - R;
    float se = 0.f, sp = 0.f, c = 0.f;
    #pragma unroll
    for (int k = 0; k < 8; k++) {
        int s = sg * 8 + k;
        int id; const float *pse, *psp, *pct;
        if (s < nd) { id = tri_base(R) + s;            pse = g_dse; psp = g_dsp; pct = g_dct; }
        else        { int I = s - nd;
                      id = tri_base(I) + (R - I);      pse = g_tse; psp = g_tsp; pct = g_tct; }
        se += pse[id * 128 + rr]; sp += psp[id * 128 + rr]; c += pct[id * 128 + rr];
    }
    s_se[sg][al] = se; s_sp[sg][al] = sp; s_ct[sg][al] = c;
    __syncthreads();
    if (tid < 32) {
        float a = 0.f, b = 0.f, cc = 0.f;
        #pragma unroll
        for (int g = 0; g < 8; g++) { a += s_se[g][tid]; b += s_sp[g][tid]; cc += s_ct[g][tid]; }
        float lse = logf(a) + 10.0f;
        float L = 0.f, V = 0.f;
        if (cc > 0.0f) { L = -(10.0f * b - cc * lse) / cc; V = 1.0f; }   // sp stored as Σsim
        #pragma unroll
        for (int o = 16; o; o >>= 1) {
            L += __shfl_down_sync(0xffffffffu, L, o);
            V += __shfl_down_sync(0xffffffffu, V, o);
        }
        if (tid == 0) { g_partL[blockIdx.x] = L; g_partV[blockIdx.x] = V; }
    }
}

__global__ void final_combine_kernel(float* __restrict__ out) {
    __shared__ float sA[8], sB[8];
    int tid = threadIdx.x;   // 256 threads
    float a = g_partL[tid], b = g_partV[tid];
    #pragma unroll
    for (int o = 16; o; o >>= 1) {
        a += __shfl_down_sync(0xffffffffu, a, o);
        b += __shfl_down_sync(0xffffffffu, b, o);
    }
    if ((tid & 31) == 0) { sA[tid >> 5] = a; sB[tid >> 5] = b; }
    __syncthreads();
    if (tid == 0) {
        float ta = 0.f, tb = 0.f;
        #pragma unroll
        for (int w = 0; w < 8; w++) { ta += sA[w]; tb += sB[w]; }
        out[0] = ta / fmaxf(tb, 1.0f);
    }
}

// ---------------- launch ----------------
extern "C" void kernel_launch(void* const* d_in, const int* in_sizes, int n_in,
                              void* d_out, int out_size) {
    const float* h   = (const float*)d_in[0];
    const float* pos = (const float*)d_in[1];
    if (n_in >= 2 && in_sizes[0] < in_sizes[1]) {
        const float* t = h; h = pos; pos = t;
    }
    float* out = (float*)d_out;

    prep_kernel<<<N / 8, 256>>>(h, pos);

    cudaFuncSetAttribute(main_kernel, cudaFuncAttributeMaxDynamicSharedMemorySize, SMEM_REQ);
    main_kernel<<<NCTAS, 256, SMEM_REQ>>>();

    final_partial_kernel<<<256, 256>>>();
    final_combine_kernel<<<1, 256>>>(out);
}

// round 12
// speedup vs baseline: 1.2319x; 1.0112x over previous
#include <cuda_runtime.h>
#include <cuda_fp16.h>
#include <cstdint>

#define N 8192
#define D 128
#define NBLK 64               // 64 tiles of 128 rows/cols
#define TILEB 32768           // one 128x128 fp16 tile, bytes
#define NCTA 2080             // upper-triangle tile pairs (64*65/2)
#define NCTAS 304             // persistent CTAs: 2 per SM on 152 SMs
#define EPS2 0.25f
#define TENLOG2E 14.426950408889634f

// ---------------- device scratch ----------------
__device__ uint4  g_hf[NBLK * 2048];   // fp16 tiles, ldmatrix-swizzled
__device__ float4 g_pos4[N];           // (x,y,z,|p|^2)
__device__ float  g_dse[NCTA * 128], g_dsp[NCTA * 128], g_dct[NCTA * 128];  // row (block I) partials
__device__ float  g_tse[NCTA * 128], g_tsp[NCTA * 128], g_tct[NCTA * 128];  // col (block J) partials
__device__ float  g_partL[256], g_partV[256];
__device__ int    g_done;

// ---------------- portable PTX helpers ----------------
#define CP16(dst, src) \
    asm volatile("cp.async.cg.shared.global [%0], [%1], 16;\n" :: "r"(dst), "l"(src) : "memory")
#define CP_COMMIT() asm volatile("cp.async.commit_group;\n" ::: "memory")
#define CP_WAIT0()  asm volatile("cp.async.wait_group 0;\n" ::: "memory")

#define LDSM4(r0, r1, r2, r3, addr) \
    asm volatile("ldmatrix.sync.aligned.m8n8.x4.shared.b16 {%0,%1,%2,%3}, [%4];" \
                 : "=r"(r0), "=r"(r1), "=r"(r2), "=r"(r3) : "r"(addr))

#define MMA16816(d, a, b0, b1) \
    asm volatile("mma.sync.aligned.m16n8k16.row.col.f32.f16.f16.f32 " \
                 "{%0,%1,%2,%3}, {%4,%5,%6,%7}, {%8,%9}, {%0,%1,%2,%3};" \
                 : "+f"((d)[0]), "+f"((d)[1]), "+f"((d)[2]), "+f"((d)[3]) \
                 : "r"((a)[0]), "r"((a)[1]), "r"((a)[2]), "r"((a)[3]), "r"(b0), "r"(b1))

#define PACK2(out, lo, hi) asm("mov.b64 %0, {%1, %2};" : "=l"(out) : "f"(lo), "f"(hi))
#define UNPACK2(lo, hi, in) asm("mov.b64 {%0, %1}, %2;" : "=f"(lo), "=f"(hi) : "l"(in))
#define ADD2(c, a) asm("add.rn.f32x2 %0, %0, %1;" : "+l"(c) : "l"(a))
#define EX2(e, arg) asm("ex2.approx.ftz.f32 %0, %1;" : "=f"(e) : "f"(arg))

__device__ __host__ __forceinline__ uint32_t swz(uint32_t x, uint32_t c16) {
    return (c16 & 8u) | ((c16 & 7u) ^ x);
}

// ---------------- prep: normalize + fp16 convert + swizzled store + pos pack ----------------
__global__ void prep_kernel(const float* __restrict__ h, const float* __restrict__ pos) {
    if (blockIdx.x == 0 && threadIdx.x == 0) g_done = 0;   // reset merged-final counter
    int row  = blockIdx.x * 8 + (threadIdx.x >> 5);
    int lane = threadIdx.x & 31;
    float4 v = ((const float4*)h)[row * 32 + lane];
    float ss = v.x * v.x + v.y * v.y + v.z * v.z + v.w * v.w;
    #pragma unroll
    for (int o = 16; o; o >>= 1) ss += __shfl_xor_sync(0xffffffffu, ss, o);
    float inv = 1.0f / fmaxf(sqrtf(ss), 1e-12f);
    float x[4] = {v.x * inv, v.y * inv, v.z * inv, v.w * inv};
    unsigned short hb[4];
    #pragma unroll
    for (int j = 0; j < 4; j++) hb[j] = __half_as_ushort(__float2half_rn(x[j]));
    uint2 hu = make_uint2((uint32_t)hb[0] | ((uint32_t)hb[1] << 16),
                          (uint32_t)hb[2] | ((uint32_t)hb[3] << 16));
    int blk = row >> 7, r = row & 127;
    uint32_t c16 = (uint32_t)(lane >> 1);
    uint32_t soff = (uint32_t)r * 256u + swz((uint32_t)(r & 7), c16) * 16u
                    + (uint32_t)(lane & 1) * 8u;
    *(uint2*)((char*)g_hf + (size_t)blk * TILEB + soff) = hu;
    if (lane == 0) {
        float px = pos[3 * row], py = pos[3 * row + 1], pz = pos[3 * row + 2];
        g_pos4[row] = make_float4(px, py, pz, px * px + py * py + pz * pz);
    }
}

// ---------------- main kernel: persistent, pipelined tile pairs, occ 2 ----------------
// smem: A 0..32K | B buf0 32K..64K | B buf1 64K..96K | red @96K (9216 B)
#define ASM 0
#define BBUF(b) (32768 + (b) * 32768)
#define RED 98304
#define SMEM_REQ (RED + 9216)   // 107520

__device__ __forceinline__ void load_tile16(uint32_t dst, int blk, int tid) {
    const char* gh = (const char*)g_hf + (size_t)blk * TILEB;
    #pragma unroll
    for (int i = 0; i < 8; i++) {
        uint32_t o = (uint32_t)(tid * 128 + i * 16);
        CP16(dst + o, gh + o);
    }
}

__global__ void __launch_bounds__(256, 2) main_kernel() {
    extern __shared__ __align__(128) char smem[];
    const uint32_t sbase = (uint32_t)__cvta_generic_to_shared(smem);
    float* rbuf_se = (float*)(smem + RED);
    float* rbuf_sp = rbuf_se + 512;
    float* rbuf_ct = rbuf_sp + 512;
    float* cbuf_se = rbuf_ct + 512;
    float* cbuf_sp = cbuf_se + 256;
    float* cbuf_ct = cbuf_sp + 256;

    const int tid = threadIdx.x, wid = tid >> 5, lane = tid & 31;
    const int warpRow = wid >> 2, warpCol = wid & 3;

    const int p0 = (int)((long long)blockIdx.x * NCTA / NCTAS);
    const int p1 = (int)((long long)(blockIdx.x + 1) * NCTA / NCTAS);
    if (p0 >= p1) return;

    // decode p0 -> (I, J)
    int I = 0, t = p0;
    while (t >= NBLK - I) { t -= NBLK - I; I++; }
    int J = I + t;

    // ---- fragment address constants ----
    uint32_t aAddr[4], axr[4];
    #pragma unroll
    for (int mt = 0; mt < 4; mt++) {
        uint32_t r = (uint32_t)(warpRow * 64 + mt * 16 + (lane & 15));
        aAddr[mt] = sbase + ASM + r * 256u;
        axr[mt]   = r & 7u;
    }
    const uint32_t aSel = (uint32_t)((lane >> 4) & 1);
    uint32_t bOff[2], bxr[2];
    #pragma unroll
    for (int ntp = 0; ntp < 2; ntp++) {
        uint32_t n = (uint32_t)(warpCol * 32 + ntp * 16 + ((lane >> 4) & 1) * 8 + (lane & 7));
        bOff[ntp] = n * 256u;
        bxr[ntp]  = n & 7u;
    }
    const uint32_t bSel = (uint32_t)((lane >> 3) & 1);

    // ---- prologue: A(I) + B(J) into buf 0 ----
    load_tile16(sbase + ASM, I, tid);
    load_tile16(sbase + BBUF(0), J, tid);
    CP_COMMIT();

    int buf = 0;
    for (int p = p0; p < p1; p++) {
        int nI = I, nJ = J + 1;
        if (nJ == NBLK) { nI = I + 1; nJ = nI; }
        const bool havenext = (p + 1 < p1);
        const bool nextSame = havenext && (nI == I);

        CP_WAIT0();
        __syncthreads();

        if (nextSame) {                         // prefetch overlaps the GEMM
            load_tile16(sbase + BBUF(buf ^ 1), nJ, tid);
            CP_COMMIT();
        }

        const uint32_t baseB = sbase + BBUF(buf);

        float acc[4][4][4];
        #pragma unroll
        for (int mt = 0; mt < 4; mt++)
            #pragma unroll
            for (int nt = 0; nt < 4; nt++)
                #pragma unroll
                for (int c = 0; c < 4; c++) acc[mt][nt][c] = 0.f;

        // ---- single-pass fp16 GEMM ----
        #pragma unroll 2
        for (int step = 0; step < 8; step++) {
            const uint32_t c16a = (uint32_t)(2 * step) + aSel;
            const uint32_t c16b = (uint32_t)(2 * step) + bSel;
            uint32_t bh[2][4], af[4][4];
            #pragma unroll
            for (int ntp = 0; ntp < 2; ntp++) {
                uint32_t sw = swz(bxr[ntp], c16b) << 4;
                LDSM4(bh[ntp][0], bh[ntp][1], bh[ntp][2], bh[ntp][3], baseB + bOff[ntp] + sw);
            }
            #pragma unroll
            for (int mt = 0; mt < 4; mt++) {
                uint32_t sw = swz(axr[mt], c16a) << 4;
                LDSM4(af[mt][0], af[mt][1], af[mt][2], af[mt][3], aAddr[mt] + sw);
            }
            #pragma unroll
            for (int mt = 0; mt < 4; mt++)
                #pragma unroll
                for (int nt = 0; nt < 4; nt++)
                    MMA16816(acc[mt][nt], af[mt], bh[nt >> 1][(nt & 1) * 2], bh[nt >> 1][(nt & 1) * 2 + 1]);
        }

        __syncthreads();   // all warps done reading A and B[buf]

        if (havenext && !nextSame) {            // A-transition overlaps the epilogue
            load_tile16(sbase + ASM, nI, tid);
            load_tile16(sbase + BBUF(buf ^ 1), nJ, tid);
            CP_COMMIT();
        }

        // ---- epilogue ----
        const int rowBase = I * 128, colBase0 = J * 128;
        const bool diag = (I == J);
        float cse[8];
        unsigned long long cpk[8];              // packed (Σsim_pos, count) per col
        #pragma unroll
        for (int i = 0; i < 8; i++) { cse[i] = 0.f; cpk[i] = 0ull; }
        float4 pb[8];
        #pragma unroll
        for (int nt = 0; nt < 4; nt++)
            #pragma unroll
            for (int ce = 0; ce < 2; ce++)
                pb[nt * 2 + ce] = __ldg(&g_pos4[colBase0 + warpCol * 32 + nt * 8 + (lane & 3) * 2 + ce]);

        #pragma unroll
        for (int mt = 0; mt < 4; mt++) {
            #pragma unroll
            for (int rs = 0; rs < 2; rs++) {
                const int gi = rowBase + warpRow * 64 + mt * 16 + (lane >> 2) + rs * 8;
                const float4 A = __ldg(&g_pos4[gi]);
                const float nAx = -2.0f * A.x, nAy = -2.0f * A.y, nAz = -2.0f * A.z;
                float a_se = 0.f;
                unsigned long long a_pk = 0ull;
                if (!diag) {
                    #pragma unroll
                    for (int nt = 0; nt < 4; nt++) {
                        #pragma unroll
                        for (int ce = 0; ce < 2; ce++) {
                            float sim = acc[mt][nt][rs * 2 + ce];
                            float e, arg = fmaf(sim, TENLOG2E, -TENLOG2E);
                            EX2(e, arg);
                            float4 B = pb[nt * 2 + ce];
                            float d2 = fmaf(nAx, B.x, fmaf(nAy, B.y, fmaf(nAz, B.z, A.w + B.w)));
                            unsigned long long pk;
                            PACK2(pk, sim, 1.0f);
                            pk = (d2 < EPS2) ? pk : 0ull;
                            a_se += e;  ADD2(a_pk, pk);
                            int ci = nt * 2 + ce;
                            cse[ci] += e;  ADD2(cpk[ci], pk);
                        }
                    }
                } else {
                    #pragma unroll
                    for (int nt = 0; nt < 4; nt++) {
                        #pragma unroll
                        for (int ce = 0; ce < 2; ce++) {
                            float sim = acc[mt][nt][rs * 2 + ce];
                            int j = colBase0 + warpCol * 32 + nt * 8 + (lane & 3) * 2 + ce;
                            float e, arg = fmaf(sim, TENLOG2E, -TENLOG2E);
                            EX2(e, arg);
                            float4 B = pb[nt * 2 + ce];
                            float d2 = fmaf(nAx, B.x, fmaf(nAy, B.y, fmaf(nAz, B.z, A.w + B.w)));
                            bool self = (gi == j);
                            float ev = self ? 0.0f : e;
                            unsigned long long pk;
                            PACK2(pk, sim, 1.0f);
                            pk = ((d2 < EPS2) && !self) ? pk : 0ull;
                            a_se += ev;  ADD2(a_pk, pk);
                            int ci = nt * 2 + ce;
                            cse[ci] += ev;  ADD2(cpk[ci], pk);
                        }
                    }
                }
                // row reduce over the 4 lanes (lane&3) sharing this row
                a_se += __shfl_down_sync(0xffffffffu, a_se, 2, 4);
                a_pk  = __shfl_down_sync(0xffffffffu, a_pk, 2, 4) + 0ull,
                a_pk  = a_pk;   // (keep as u64 shfl below)
                {
                    unsigned long long s2 = __shfl_down_sync(0xffffffffu, a_pk, 2, 4);
                    ADD2(a_pk, s2);
                    a_se += __shfl_down_sync(0xffffffffu, a_se, 1, 4);
                    unsigned long long s1 = __shfl_down_sync(0xffffffffu, a_pk, 1, 4);
                    ADD2(a_pk, s1);
                }
                if ((lane & 3) == 0) {
                    int rl = mt * 16 + rs * 8 + (lane >> 2);
                    float sp, ct;
                    UNPACK2(sp, ct, a_pk);
                    rbuf_se[wid * 64 + rl] = a_se;
                    rbuf_sp[wid * 64 + rl] = sp;
                    rbuf_ct[wid * 64 + rl] = ct;
                }
            }
        }

        // col reduce: 8 lanes (lane>>2) share each column
        #pragma unroll
        for (int ci = 0; ci < 8; ci++) {
            float a = cse[ci];
            unsigned long long pk = cpk[ci];
            #pragma unroll
            for (int o = 16; o >= 4; o >>= 1) {
                a += __shfl_down_sync(0xffffffffu, a, o);
                unsigned long long s = __shfl_down_sync(0xffffffffu, pk, o);
                ADD2(pk, s);
            }
            if (lane < 4) {
                int cl = (ci >> 1) * 8 + lane * 2 + (ci & 1);
                float sp, ct;
                UNPACK2(sp, ct, pk);
                cbuf_se[wid * 32 + cl] = a;
                cbuf_sp[wid * 32 + cl] = sp;
                cbuf_ct[wid * 32 + cl] = ct;
            }
        }
        __syncthreads();

        // combine across warps, write deterministic per-pair slots
        const int slot = p * 128;
        if (tid < 128) {
            int half = tid >> 6, loc = tid & 63;
            float a = 0.f, b = 0.f, c = 0.f;
            #pragma unroll
            for (int wc = 0; wc < 4; wc++) {
                int w = half * 4 + wc;
                a += rbuf_se[w * 64 + loc];
                b += rbuf_sp[w * 64 + loc];
                c += rbuf_ct[w * 64 + loc];
            }
            g_dse[slot + tid] = a; g_dsp[slot + tid] = b; g_dct[slot + tid] = c;
        } else if (!diag) {
            int tcl = tid - 128, wc = tcl >> 5, c5 = tcl & 31;
            float a = cbuf_se[wc * 32 + c5] + cbuf_se[(4 + wc) * 32 + c5];
            float b = cbuf_sp[wc * 32 + c5] + cbuf_sp[(4 + wc) * 32 + c5];
            float c = cbuf_ct[wc * 32 + c5] + cbuf_ct[(4 + wc) * 32 + c5];
            g_tse[slot + tcl] = a; g_tsp[slot + tcl] = b; g_tct[slot + tcl] = c;
        }

        I = nI; J = nJ; buf ^= 1;
    }
}

// ---------------- final: triangle-slot reduction + merged scalar combine ----------------
__device__ __forceinline__ int tri_base(int I) { return I * NBLK - (I * (I - 1)) / 2; }

// grid 256 (R = blockIdx>>2 constant per block), block 256:
// tid = (slotGroup<<5) | anchorLocal; each thread sums 8 of the 64 slots.
// Last finishing block combines all 256 partials (deterministic: single block).
__global__ void final_kernel(float* __restrict__ out) {
    __shared__ float s_se[8][32], s_sp[8][32], s_ct[8][32];
    __shared__ int s_last;
    const int tid = threadIdx.x;
    const int al = tid & 31, sg = tid >> 5;
    const int R = blockIdx.x >> 2;
    const int rr = (blockIdx.x & 3) * 32 + al;
    const int nd = NBLK - R;
    float se = 0.f, sp = 0.f, c = 0.f;
    #pragma unroll
    for (int k = 0; k < 8; k++) {
        int s = sg * 8 + k;
        int id; const float *pse, *psp, *pct;
        if (s < nd) { id = tri_base(R) + s;            pse = g_dse; psp = g_dsp; pct = g_dct; }
        else        { int I = s - nd;
                      id = tri_base(I) + (R - I);      pse = g_tse; psp = g_tsp; pct = g_tct; }
        se += pse[id * 128 + rr]; sp += psp[id * 128 + rr]; c += pct[id * 128 + rr];
    }
    s_se[sg][al] = se; s_sp[sg][al] = sp; s_ct[sg][al] = c;
    __syncthreads();
    if (tid < 32) {
        float a = 0.f, b = 0.f, cc = 0.f;
        #pragma unroll
        for (int g = 0; g < 8; g++) { a += s_se[g][tid]; b += s_sp[g][tid]; cc += s_ct[g][tid]; }
        float lse = logf(a) + 10.0f;
        float L = 0.f, V = 0.f;
        if (cc > 0.0f) { L = -(10.0f * b - cc * lse) / cc; V = 1.0f; }   // sp stored as Σsim
        #pragma unroll
        for (int o = 16; o; o >>= 1) {
            L += __shfl_down_sync(0xffffffffu, L, o);
            V += __shfl_down_sync(0xffffffffu, V, o);
        }
        if (tid == 0) { g_partL[blockIdx.x] = L; g_partV[blockIdx.x] = V; }
    }
    // last-block combine
    __threadfence();
    __syncthreads();
    if (tid == 0) s_last = (atomicAdd(&g_done, 1) == (int)gridDim.x - 1);
    __syncthreads();
    if (s_last) {
        float a = g_partL[tid], b = g_partV[tid];
        #pragma unroll
        for (int o = 16; o; o >>= 1) {
            a += __shfl_down_sync(0xffffffffu, a, o);
            b += __shfl_down_sync(0xffffffffu, b, o);
        }
        if ((tid & 31) == 0) { s_se[0][tid >> 5] = a; s_sp[0][tid >> 5] = b; }
        __syncthreads();
        if (tid == 0) {
            float ta = 0.f, tb = 0.f;
            #pragma unroll
            for (int w = 0; w < 8; w++) { ta += s_se[0][w]; tb += s_sp[0][w]; }
            out[0] = ta / fmaxf(tb, 1.0f);
        }
    }
}

// ---------------- launch ----------------
extern "C" void kernel_launch(void* const* d_in, const int* in_sizes, int n_in,
                              void* d_out, int out_size) {
    const float* h   = (const float*)d_in[0];
    const float* pos = (const float*)d_in[1];
    if (n_in >= 2 && in_sizes[0] < in_sizes[1]) {
        const float* t = h; h = pos; pos = t;
    }
    float* out = (float*)d_out;

    prep_kernel<<<N / 8, 256>>>(h, pos);

    cudaFuncSetAttribute(main_kernel, cudaFuncAttributeMaxDynamicSharedMemorySize, SMEM_REQ);
    main_kernel<<<NCTAS, 256, SMEM_REQ>>>();

    final_kernel<<<256, 256>>>(out);
}